// round 8
// baseline (speedup 1.0000x reference)
#include <cuda_runtime.h>
#include <cuda_bf16.h>

#define G_MAX 128
#define BLOCK 256

__global__ __launch_bounds__(BLOCK)
void roi_match_kernel(const float4* __restrict__ props,
                      const float4* __restrict__ gt,
                      const int*    __restrict__ gtl32,   // gt labels, i32 or i64 (auto-detect)
                      float*        __restrict__ out_labels,
                      float4*       __restrict__ out_boxes,
                      int N, int G)
{
    __shared__ float4 s_gt[G_MAX];
    __shared__ float  s_area[G_MAX];
    __shared__ float  s_lab[G_MAX];

    const int t = threadIdx.x;
    if (t < G) {
        float4 b = gt[t];
        s_gt[t]   = b;
        s_area[t] = __fmul_rn(__fsub_rn(b.z, b.x), __fsub_rn(b.w, b.y));
        // labels >= 1, so little-endian i64 => word 1 (hi word of elem 0) == 0
        int is64 = (gtl32[1] == 0) ? 1 : 0;
        s_lab[t] = (float)gtl32[is64 ? (2 * t) : t];
    }
    __syncthreads();

    const int n  = blockIdx.x * BLOCK + t;
    const int ni = (n < N) ? n : (N - 1);       // clamp tail loads; store guarded

    const float4 p = props[ni];
    const float parea = __fmul_rn(__fsub_rn(p.z, p.x), __fsub_rn(p.w, p.y));

    // ---- Phase 1: exact overlap mask (inter > 0 <=> strict interval overlap).
    // For IEEE floats, fl(a-b) == 0 iff a == b (no underflow in this range),
    // so   min(gz,pz) > max(gx,px)  <=>  clamped dx > 0. Culled pairs have
    // inter == 0 exactly and can never beat the sentinel below -> bit-exact.
    unsigned msk[4];
    #pragma unroll 1
    for (int w = 0; w < 4; ++w) {
        unsigned m = 0;
        #pragma unroll
        for (int k = 0; k < 32; ++k) {
            const float4 gb = s_gt[w * 32 + k];   // broadcast LDS (conflict-free)
            bool ov = (fminf(gb.z, p.z) > fmaxf(gb.x, p.x)) &&
                      (fminf(gb.w, p.w) > fmaxf(gb.y, p.y));
            if (ov) m |= (1u << k);               // compile-time immediate
        }
        msk[w] = m;
    }

    // Sentinel: bestI=0, bestS=1 -> first strict comparison reduces to inter>0;
    // an all-culled (all-zero) row yields idx 0, iou = 0/(1-0) = 0 -> label -1,
    // box gt[0], matching jnp.argmax-of-zeros.
    float bestI = 0.0f, bestS = 1.0f;
    int bestIdx = 0;

    // ---- Phase 2: exact IoU-argmax over survivors, ascending g (ffs from LSB,
    // words in order) so strict > keeps the first max (jnp.argmax semantics).
    #pragma unroll 1
    for (int w = 0; w < 4; ++w) {
        unsigned m = msk[w];
        while (m) {
            const int k = __ffs(m) - 1;
            m &= m - 1;
            const int g = w * 32 + k;
            const float4 gb = s_gt[g];
            float x1 = fmaxf(gb.x, p.x);
            float y1 = fmaxf(gb.y, p.y);
            float x2 = fminf(gb.z, p.z);
            float y2 = fminf(gb.w, p.w);
            float dx = fmaxf(__fsub_rn(x2, x1), 0.0f);
            float dy = fmaxf(__fsub_rn(y2, y1), 0.0f);
            float inter = __fmul_rn(dx, dy);
            float S     = __fadd_rn(s_area[g], parea);   // area_g + parea
            // iou = inter/(S - inter) monotone in inter/S (S > 0):
            //   i1/(S1-i1) > i2/(S2-i2)  <=>  i1*S2 > i2*S1  (cross terms cancel)
            // FFMA gives the sign of the cross-difference to ~1 ulp; strict >
            // keeps the earlier index.
            float d = __fmaf_rn(inter, bestS, -__fmul_rn(bestI, S));
            bool take = d > 0.0f;
            bestI   = take ? inter : bestI;
            bestS   = take ? S     : bestS;
            bestIdx = take ? g     : bestIdx;
        }
    }

    if (n < N) {
        // uni = fl(bestS - bestI) == reference's fl(fl(a1+a2) - inter);
        // single IEEE division -> bitwise-equal iou for the winning pair.
        float uni = __fsub_rn(bestS, bestI);
        float iou = __fdiv_rn(bestI, uni);
        float lab = s_lab[bestIdx];
        if (iou < 0.5f) lab = (iou >= 0.1f) ? 0.0f : -1.0f;
        if (out_labels) out_labels[n] = lab;
        if (out_boxes)  out_boxes[n]  = s_gt[bestIdx];
    }
}

extern "C" void kernel_launch(void* const* d_in, const int* in_sizes, int n_in,
                              void* d_out, int out_size)
{
    const float4* props = (const float4*)d_in[0];
    const float4* gt    = (const float4*)d_in[1];
    const int*    gtl   = (const int*)d_in[2];

    const int N = in_sizes[0] / 4;
    const int G = in_sizes[1] / 4;

    float*  out       = (float*)d_out;
    float*  out_label = nullptr;
    float4* out_boxes = nullptr;

    if (out_size == 5 * N) {            // [labels (N) ; boxes (4N)] as f32
        out_label = out;
        out_boxes = (float4*)(out + N); // 16B-aligned since N % 4 == 0
    } else if (out_size == 4 * N) {     // boxes only
        out_boxes = (float4*)out;
    } else {                            // labels only
        out_label = out;
    }

    const int grid = (N + BLOCK - 1) / BLOCK;
    roi_match_kernel<<<grid, BLOCK>>>(props, gt, gtl, out_label, out_boxes, N, G);
}